// round 3
// baseline (speedup 1.0000x reference)
#include <cuda_runtime.h>
#include <cuda_bf16.h>

// Problem constants
#define T_STEPS 480000
#define LAYER   32
#define C1_CONST 4.7e-9f

// Per-step packed parameters (2 x float4 per step):
//  params[2t]   = { row0.x (=P0-1), row0.y (=P1), row0.z*v, dp_r }
//  params[2t+1] = { row1.x (=P0),   row1.y (=P1-1), row1.z*v, 0 }
__device__ float4 g_params[2 * T_STEPS];

// ---------------------------------------------------------------------------
// Kernel 1: embarrassingly-parallel precompute of WDF port parameters
// ---------------------------------------------------------------------------
__global__ void ndc_precompute_kernel(const float* __restrict__ v_in,
                                      const float* __restrict__ vs_r,
                                      const float* __restrict__ fs,
                                      int T) {
    int t = blockIdx.x * blockDim.x + threadIdx.x;
    if (t >= T) return;

    float f  = fs[t];
    float vr = vs_r[t];
    float v  = v_in[t];

    float c1r = 1.0f / (2.0f * C1_CONST * f);
    float r0  = (c1r * vr) / (c1r + vr);

    float g0 = 1.0f / r0;
    float g1 = 1.0f / c1r;
    float g2 = 1.0f / vr;
    float s  = g0 + g1 + g2;
    float inv2 = 2.0f / s;

    float P0 = g0 * inv2;
    float P1 = g1 * inv2;
    float P2 = g2 * inv2;

    float dpr = r0 * (1.0f / 3000.0f);

    g_params[2 * t]     = make_float4(P0 - 1.0f, P1,        P2 * v, dpr);
    g_params[2 * t + 1] = make_float4(P0,        P1 - 1.0f, P2 * v, 0.0f);
}

// ---------------------------------------------------------------------------
// Kernel 2: serial recurrence. ONE warp. Thread i owns hidden unit i.
// Weights held in registers; activations broadcast via __shfl_sync.
// ---------------------------------------------------------------------------
__global__ void __launch_bounds__(32, 1)
ndc_sequential_kernel(const float* __restrict__ W_in,   // [32,2]
                      const float* __restrict__ b_in,   // [32]
                      const float* __restrict__ W_h,    // [2,32,32]
                      const float* __restrict__ b_h,    // [2,32]
                      const float* __restrict__ W_out,  // [1,32]
                      const float* __restrict__ b_out,  // [1]
                      float* __restrict__ out,          // [T]
                      int T) {
    const int lane = threadIdx.x;
    const unsigned FULL = 0xffffffffu;

    // Load weights into registers
    float win0 = W_in[lane * 2 + 0];
    float win1 = W_in[lane * 2 + 1];
    float bi   = b_in[lane];

    float w1[LAYER], w2[LAYER];
#pragma unroll
    for (int j = 0; j < LAYER; ++j) w1[j] = W_h[lane * LAYER + j];
#pragma unroll
    for (int j = 0; j < LAYER; ++j) w2[j] = W_h[LAYER * LAYER + lane * LAYER + j];

    float bh1 = b_h[lane];
    float bh2 = b_h[LAYER + lane];
    float wo  = W_out[lane];
    float bo  = b_out[0];

    // Carry
    float a0 = 0.0f;   // prev dp_b
    float b1 = 0.0f;   // prev p1_b[1]

    // Prefetch step 0 params
    float4 pA = g_params[0];
    float4 pB = g_params[1];

    for (int t = 0; t < T; ++t) {
        // Prefetch next step's params early (hide L1 latency)
        int tn = (t + 1 < T) ? (t + 1) : t;
        float4 nA = g_params[2 * tn];
        float4 nB = g_params[2 * tn + 1];

        // dp_a = row0 . [a0, b1, v]
        float dp_a = fmaf(pA.x, a0, fmaf(pA.y, b1, pA.z));

        // Input layer: h = relu(W_in @ [dp_a, drt] + b_in)
        float h = fmaxf(fmaf(win0, dp_a, fmaf(win1, pA.w, bi)), 0.0f);

        // Hidden layer 1: h2[i] = relu(sum_j w1[i][j] * h[j] + bh1[i])
        {
            float acc0 = bh1, acc1 = 0.0f, acc2 = 0.0f, acc3 = 0.0f;
#pragma unroll
            for (int j = 0; j < LAYER; j += 4) {
                acc0 = fmaf(w1[j + 0], __shfl_sync(FULL, h, j + 0), acc0);
                acc1 = fmaf(w1[j + 1], __shfl_sync(FULL, h, j + 1), acc1);
                acc2 = fmaf(w1[j + 2], __shfl_sync(FULL, h, j + 2), acc2);
                acc3 = fmaf(w1[j + 3], __shfl_sync(FULL, h, j + 3), acc3);
            }
            h = fmaxf((acc0 + acc1) + (acc2 + acc3), 0.0f);
        }

        // Hidden layer 2
        {
            float acc0 = bh2, acc1 = 0.0f, acc2 = 0.0f, acc3 = 0.0f;
#pragma unroll
            for (int j = 0; j < LAYER; j += 4) {
                acc0 = fmaf(w2[j + 0], __shfl_sync(FULL, h, j + 0), acc0);
                acc1 = fmaf(w2[j + 1], __shfl_sync(FULL, h, j + 1), acc1);
                acc2 = fmaf(w2[j + 2], __shfl_sync(FULL, h, j + 2), acc2);
                acc3 = fmaf(w2[j + 3], __shfl_sync(FULL, h, j + 3), acc3);
            }
            h = fmaxf((acc0 + acc1) + (acc2 + acc3), 0.0f);
        }

        // Output layer: dp_b = sum_i wo[i]*h[i] + bo  (butterfly reduce -> all lanes)
        float y = wo * h;
        y += __shfl_xor_sync(FULL, y, 16);
        y += __shfl_xor_sync(FULL, y, 8);
        y += __shfl_xor_sync(FULL, y, 4);
        y += __shfl_xor_sync(FULL, y, 2);
        y += __shfl_xor_sync(FULL, y, 1);
        float dp_b = y + bo;

        // Output sample
        if (lane == 0) out[t] = 0.5f * (dp_a + dp_b);

        // Carry update: b1n = row1 . [dp_b, b1, v]
        b1 = fmaf(pB.x, dp_b, fmaf(pB.y, b1, pB.z));
        a0 = dp_b;

        pA = nA;
        pB = nB;
    }
}

// ---------------------------------------------------------------------------
// Launch
// ---------------------------------------------------------------------------
extern "C" void kernel_launch(void* const* d_in, const int* in_sizes, int n_in,
                              void* d_out, int out_size) {
    const float* v_in  = (const float*)d_in[0];
    const float* vs_r  = (const float*)d_in[1];
    const float* fs    = (const float*)d_in[2];
    const float* W_in  = (const float*)d_in[3];
    const float* b_in  = (const float*)d_in[4];
    const float* W_h   = (const float*)d_in[5];
    const float* b_h   = (const float*)d_in[6];
    const float* W_out = (const float*)d_in[7];
    const float* b_out = (const float*)d_in[8];
    float* out = (float*)d_out;

    const int T = in_sizes[0];

    ndc_precompute_kernel<<<(T + 255) / 256, 256>>>(v_in, vs_r, fs, T);
    ndc_sequential_kernel<<<1, 32>>>(W_in, b_in, W_h, b_h, W_out, b_out, out, T);
}

// round 5
// speedup vs baseline: 2.0860x; 2.0860x over previous
#include <cuda_runtime.h>
#include <cuda_bf16.h>

#define T_STEPS 480000
#define LAYER   32
#define C1_CONST 4.7e-9f

// Per-step packed parameters (2 x float4 per step):
//  params[2t]   = { P0-1, P1,   P2*v, dp_r }
//  params[2t+1] = { P0,   P1-1, P2*v, 0    }
__device__ float4 g_params[2 * T_STEPS];

// ---------------------------------------------------------------------------
// packed f32x2 helpers (Blackwell FFMA2 path — only reachable via PTX)
// ---------------------------------------------------------------------------
__device__ __forceinline__ unsigned long long pack2(float lo, float hi) {
    unsigned long long r;
    asm("mov.b64 %0, {%1, %2};" : "=l"(r) : "f"(lo), "f"(hi));
    return r;
}
__device__ __forceinline__ void unpack2(unsigned long long v, float& lo, float& hi) {
    asm("mov.b64 {%0, %1}, %2;" : "=f"(lo), "=f"(hi) : "l"(v));
}
__device__ __forceinline__ unsigned long long ffma2(unsigned long long a,
                                                    unsigned long long b,
                                                    unsigned long long c) {
    unsigned long long d;
    asm("fma.rn.f32x2 %0, %1, %2, %3;" : "=l"(d) : "l"(a), "l"(b), "l"(c));
    return d;
}
__device__ __forceinline__ unsigned long long fadd2(unsigned long long a,
                                                    unsigned long long b) {
    unsigned long long d;
    asm("add.rn.f32x2 %0, %1, %2;" : "=l"(d) : "l"(a), "l"(b));
    return d;
}

// ---------------------------------------------------------------------------
// Kernel 1: parallel precompute of WDF port parameters
// ---------------------------------------------------------------------------
__global__ void ndc_precompute_kernel(const float* __restrict__ v_in,
                                      const float* __restrict__ vs_r,
                                      const float* __restrict__ fs,
                                      int T) {
    int t = blockIdx.x * blockDim.x + threadIdx.x;
    if (t >= T) return;

    float f  = fs[t];
    float vr = vs_r[t];
    float v  = v_in[t];

    float c1r = 1.0f / (2.0f * C1_CONST * f);
    float r0  = (c1r * vr) / (c1r + vr);

    float g0 = 1.0f / r0;
    float g1 = 1.0f / c1r;
    float g2 = 1.0f / vr;
    float inv2 = 2.0f / (g0 + g1 + g2);

    float P0 = g0 * inv2;
    float P1 = g1 * inv2;
    float P2 = g2 * inv2;

    float dpr = r0 * (1.0f / 3000.0f);

    g_params[2 * t]     = make_float4(P0 - 1.0f, P1,        P2 * v, dpr);
    g_params[2 * t + 1] = make_float4(P0,        P1 - 1.0f, P2 * v, 0.0f);
}

// ---------------------------------------------------------------------------
// 32x32 matvec for one lane: weights packed f32x2 in registers, activations
// broadcast from shared memory as 64-bit pairs. Returns row dot + bias.
// ---------------------------------------------------------------------------
__device__ __forceinline__ float matvec_row(const unsigned long long* __restrict__ wp,
                                            const unsigned long long* __restrict__ shp,
                                            float bias) {
    // Batch all 16 broadcast loads first (independent -> pipelined LDS)
    unsigned long long hv[16];
#pragma unroll
    for (int k = 0; k < 16; ++k) hv[k] = shp[k];

    unsigned long long acc0 = pack2(bias, 0.0f);
    unsigned long long acc1 = pack2(0.0f, 0.0f);
#pragma unroll
    for (int k = 0; k < 16; k += 2) {
        acc0 = ffma2(wp[k],     hv[k],     acc0);
        acc1 = ffma2(wp[k + 1], hv[k + 1], acc1);
    }
    acc0 = fadd2(acc0, acc1);
    float lo, hi;
    unpack2(acc0, lo, hi);
    return lo + hi;
}

// ---------------------------------------------------------------------------
// Kernel 2: serial recurrence. ONE warp; lane i owns hidden unit i.
// ---------------------------------------------------------------------------
__global__ void __launch_bounds__(32, 1)
ndc_sequential_kernel(const float* __restrict__ W_in,   // [32,2]
                      const float* __restrict__ b_in,   // [32]
                      const float* __restrict__ W_h,    // [2,32,32]
                      const float* __restrict__ b_h,    // [2,32]
                      const float* __restrict__ W_out,  // [1,32]
                      const float* __restrict__ b_out,  // [1]
                      float* __restrict__ out,          // [T]
                      int T) {
    const int lane = threadIdx.x;

    __shared__ __align__(16) float sh0[LAYER];
    __shared__ __align__(16) float sh1[LAYER];
    __shared__ __align__(16) float sh2[LAYER];
    const unsigned long long* shp0 = (const unsigned long long*)sh0;
    const unsigned long long* shp1 = (const unsigned long long*)sh1;
    const unsigned long long* shp2 = (const unsigned long long*)sh2;

    // ---- load + pack weights into registers ----
    float win0 = W_in[lane * 2 + 0];
    float win1 = W_in[lane * 2 + 1];
    float bi   = b_in[lane];

    unsigned long long w1p[16], w2p[16];
#pragma unroll
    for (int k = 0; k < 16; ++k)
        w1p[k] = pack2(W_h[lane * LAYER + 2 * k], W_h[lane * LAYER + 2 * k + 1]);
#pragma unroll
    for (int k = 0; k < 16; ++k)
        w2p[k] = pack2(W_h[LAYER * LAYER + lane * LAYER + 2 * k],
                       W_h[LAYER * LAYER + lane * LAYER + 2 * k + 1]);

    float bh1 = b_h[lane];
    float bh2 = b_h[LAYER + lane];
    float wo  = W_out[lane];
    float bo  = b_out[0];

    // Carry
    float a0 = 0.0f;   // prev dp_b
    float b1 = 0.0f;   // prev p1_b[1]

    // Prefetch step-0 params
    float4 pA = g_params[0];
    float4 pB = g_params[1];

    for (int t = 0; t < T; ++t) {
        // Prefetch next step's params early (hide memory latency)
        int tn = (t + 1 < T) ? (t + 1) : t;
        float4 nA = g_params[2 * tn];
        float4 nB = g_params[2 * tn + 1];

        // dp_a = row0 . [a0, b1, v]
        float dp_a = fmaf(pA.x, a0, fmaf(pA.y, b1, pA.z));

        // Input layer: scalar per lane
        float h = fmaxf(fmaf(win0, dp_a, fmaf(win1, pA.w, bi)), 0.0f);

        // Hidden layer 1 (smem broadcast + packed FMA)
        sh0[lane] = h;
        __syncwarp();
        float h1 = fmaxf(matvec_row(w1p, shp0, bh1), 0.0f);

        // Hidden layer 2
        sh1[lane] = h1;
        __syncwarp();
        float h2 = fmaxf(matvec_row(w2p, shp1, bh2), 0.0f);

        // Output layer: every lane redundantly sums wo[j]*h2[j] (packed add tree)
        sh2[lane] = wo * h2;
        __syncwarp();
        {
            unsigned long long zv[16];
#pragma unroll
            for (int k = 0; k < 16; ++k) zv[k] = shp2[k];
            unsigned long long s0 = fadd2(zv[0], zv[1]);
            unsigned long long s1 = fadd2(zv[2], zv[3]);
            unsigned long long s2 = fadd2(zv[4], zv[5]);
            unsigned long long s3 = fadd2(zv[6], zv[7]);
            unsigned long long s4 = fadd2(zv[8], zv[9]);
            unsigned long long s5 = fadd2(zv[10], zv[11]);
            unsigned long long s6 = fadd2(zv[12], zv[13]);
            unsigned long long s7 = fadd2(zv[14], zv[15]);
            s0 = fadd2(s0, s1);  s2 = fadd2(s2, s3);
            s4 = fadd2(s4, s5);  s6 = fadd2(s6, s7);
            s0 = fadd2(s0, s2);  s4 = fadd2(s4, s6);
            s0 = fadd2(s0, s4);
            float lo, hi;
            unpack2(s0, lo, hi);
            float dp_b = lo + hi + bo;

            // Output sample
            if (lane == 0) out[t] = 0.5f * (dp_a + dp_b);

            // Carry update (uniform across lanes — identical arithmetic order)
            b1 = fmaf(pB.x, dp_b, fmaf(pB.y, b1, pB.z));
            a0 = dp_b;
        }

        pA = nA;
        pB = nB;
    }
}

// ---------------------------------------------------------------------------
// Launch
// ---------------------------------------------------------------------------
extern "C" void kernel_launch(void* const* d_in, const int* in_sizes, int n_in,
                              void* d_out, int out_size) {
    const float* v_in  = (const float*)d_in[0];
    const float* vs_r  = (const float*)d_in[1];
    const float* fs    = (const float*)d_in[2];
    const float* W_in  = (const float*)d_in[3];
    const float* b_in  = (const float*)d_in[4];
    const float* W_h   = (const float*)d_in[5];
    const float* b_h   = (const float*)d_in[6];
    const float* W_out = (const float*)d_in[7];
    const float* b_out = (const float*)d_in[8];
    float* out = (float*)d_out;

    const int T = in_sizes[0];

    ndc_precompute_kernel<<<(T + 255) / 256, 256>>>(v_in, vs_r, fs, T);
    ndc_sequential_kernel<<<1, 32>>>(W_in, b_in, W_h, b_h, W_out, b_out, out, T);
}

// round 6
// speedup vs baseline: 228.6447x; 109.6097x over previous
#include <cuda_runtime.h>
#include <cuda_bf16.h>

#define T_STEPS   480000
#define LAYER     32
#define C1_CONST  4.7e-9f
#define N_CHUNKS  148      // one CTA (one warp) per SM
#define WARMUP    1024     // state-convergence warmup steps per chunk

// Per-step packed parameters (2 x float4 per step):
//  params[2t]   = { P0-1, P1,   P2*v, dp_r }
//  params[2t+1] = { P0,   P1-1, P2*v, 0    }
__device__ float4 g_params[2 * T_STEPS];

// ---------------------------------------------------------------------------
// packed f32x2 helpers (Blackwell FFMA2 path — only reachable via PTX)
// ---------------------------------------------------------------------------
__device__ __forceinline__ unsigned long long pack2(float lo, float hi) {
    unsigned long long r;
    asm("mov.b64 %0, {%1, %2};" : "=l"(r) : "f"(lo), "f"(hi));
    return r;
}
__device__ __forceinline__ void unpack2(unsigned long long v, float& lo, float& hi) {
    asm("mov.b64 {%0, %1}, %2;" : "=f"(lo), "=f"(hi) : "l"(v));
}
__device__ __forceinline__ unsigned long long ffma2(unsigned long long a,
                                                    unsigned long long b,
                                                    unsigned long long c) {
    unsigned long long d;
    asm("fma.rn.f32x2 %0, %1, %2, %3;" : "=l"(d) : "l"(a), "l"(b), "l"(c));
    return d;
}
__device__ __forceinline__ unsigned long long fadd2(unsigned long long a,
                                                    unsigned long long b) {
    unsigned long long d;
    asm("add.rn.f32x2 %0, %1, %2;" : "=l"(d) : "l"(a), "l"(b));
    return d;
}

// ---------------------------------------------------------------------------
// Kernel 1: parallel precompute of WDF port parameters
// ---------------------------------------------------------------------------
__global__ void ndc_precompute_kernel(const float* __restrict__ v_in,
                                      const float* __restrict__ vs_r,
                                      const float* __restrict__ fs,
                                      int T) {
    int t = blockIdx.x * blockDim.x + threadIdx.x;
    if (t >= T) return;

    float f  = fs[t];
    float vr = vs_r[t];
    float v  = v_in[t];

    float c1r = 1.0f / (2.0f * C1_CONST * f);
    float r0  = (c1r * vr) / (c1r + vr);

    float g0 = 1.0f / r0;
    float g1 = 1.0f / c1r;
    float g2 = 1.0f / vr;
    float inv2 = 2.0f / (g0 + g1 + g2);

    float P0 = g0 * inv2;
    float P1 = g1 * inv2;
    float P2 = g2 * inv2;

    float dpr = r0 * (1.0f / 3000.0f);

    g_params[2 * t]     = make_float4(P0 - 1.0f, P1,        P2 * v, dpr);
    g_params[2 * t + 1] = make_float4(P0,        P1 - 1.0f, P2 * v, 0.0f);
}

// ---------------------------------------------------------------------------
// 32x32 matvec for one lane: weights packed f32x2 in registers, activations
// broadcast from shared memory as 64-bit pairs. Returns row dot + bias.
// ---------------------------------------------------------------------------
__device__ __forceinline__ float matvec_row(const unsigned long long* __restrict__ wp,
                                            const unsigned long long* __restrict__ shp,
                                            float bias) {
    unsigned long long hv[16];
#pragma unroll
    for (int k = 0; k < 16; ++k) hv[k] = shp[k];

    unsigned long long acc0 = pack2(bias, 0.0f);
    unsigned long long acc1 = pack2(0.0f, 0.0f);
#pragma unroll
    for (int k = 0; k < 16; k += 2) {
        acc0 = ffma2(wp[k],     hv[k],     acc0);
        acc1 = ffma2(wp[k + 1], hv[k + 1], acc1);
    }
    acc0 = fadd2(acc0, acc1);
    float lo, hi;
    unpack2(acc0, lo, hi);
    return lo + hi;
}

// ---------------------------------------------------------------------------
// Kernel 2: chunk-parallel recurrence. One warp per chunk (one CTA per SM).
// The WDF diode-clipper state contracts strongly per step (|pole| << 1),
// so each chunk re-converges the carry with WARMUP steps from zero state.
// Chunk 0 starts exactly at t=0 (no approximation there).
// ---------------------------------------------------------------------------
__global__ void __launch_bounds__(32, 1)
ndc_sequential_kernel(const float* __restrict__ W_in,   // [32,2]
                      const float* __restrict__ b_in,   // [32]
                      const float* __restrict__ W_h,    // [2,32,32]
                      const float* __restrict__ b_h,    // [2,32]
                      const float* __restrict__ W_out,  // [1,32]
                      const float* __restrict__ b_out,  // [1]
                      float* __restrict__ out,          // [T]
                      int T) {
    const int lane  = threadIdx.x;
    const int chunk = blockIdx.x;

    // Chunk bounds
    const int L         = (T + (int)gridDim.x - 1) / (int)gridDim.x;
    const int emit_beg  = chunk * L;
    if (emit_beg >= T) return;
    const int emit_end  = min(emit_beg + L, T);
    int t_begin         = emit_beg - WARMUP;
    if (t_begin < 0) t_begin = 0;

    __shared__ __align__(16) float sh0[LAYER];
    __shared__ __align__(16) float sh1[LAYER];
    __shared__ __align__(16) float sh2[LAYER];
    const unsigned long long* shp0 = (const unsigned long long*)sh0;
    const unsigned long long* shp1 = (const unsigned long long*)sh1;
    const unsigned long long* shp2 = (const unsigned long long*)sh2;

    // ---- load + pack weights into registers ----
    float win0 = W_in[lane * 2 + 0];
    float win1 = W_in[lane * 2 + 1];
    float bi   = b_in[lane];

    unsigned long long w1p[16], w2p[16];
#pragma unroll
    for (int k = 0; k < 16; ++k)
        w1p[k] = pack2(W_h[lane * LAYER + 2 * k], W_h[lane * LAYER + 2 * k + 1]);
#pragma unroll
    for (int k = 0; k < 16; ++k)
        w2p[k] = pack2(W_h[LAYER * LAYER + lane * LAYER + 2 * k],
                       W_h[LAYER * LAYER + lane * LAYER + 2 * k + 1]);

    float bh1 = b_h[lane];
    float bh2 = b_h[LAYER + lane];
    float wo  = W_out[lane];
    float bo  = b_out[0];

    // Carry (zero state; warmup converges it before emit_beg)
    float a0 = 0.0f;
    float b1 = 0.0f;

    // Prefetch first step's params
    float4 pA = g_params[2 * t_begin];
    float4 pB = g_params[2 * t_begin + 1];

    for (int t = t_begin; t < emit_end; ++t) {
        // Prefetch next step's params early (hide memory latency)
        int tn = (t + 1 < emit_end) ? (t + 1) : t;
        float4 nA = g_params[2 * tn];
        float4 nB = g_params[2 * tn + 1];

        // dp_a = row0 . [a0, b1, v]
        float dp_a = fmaf(pA.x, a0, fmaf(pA.y, b1, pA.z));

        // Input layer: scalar per lane
        float h = fmaxf(fmaf(win0, dp_a, fmaf(win1, pA.w, bi)), 0.0f);

        // Hidden layer 1 (smem broadcast + packed FMA)
        sh0[lane] = h;
        __syncwarp();
        float h1 = fmaxf(matvec_row(w1p, shp0, bh1), 0.0f);

        // Hidden layer 2
        sh1[lane] = h1;
        __syncwarp();
        float h2 = fmaxf(matvec_row(w2p, shp1, bh2), 0.0f);

        // Output layer: every lane redundantly sums wo[j]*h2[j] (packed add tree)
        sh2[lane] = wo * h2;
        __syncwarp();
        {
            unsigned long long zv[16];
#pragma unroll
            for (int k = 0; k < 16; ++k) zv[k] = shp2[k];
            unsigned long long s0 = fadd2(zv[0], zv[1]);
            unsigned long long s1 = fadd2(zv[2], zv[3]);
            unsigned long long s2 = fadd2(zv[4], zv[5]);
            unsigned long long s3 = fadd2(zv[6], zv[7]);
            unsigned long long s4 = fadd2(zv[8], zv[9]);
            unsigned long long s5 = fadd2(zv[10], zv[11]);
            unsigned long long s6 = fadd2(zv[12], zv[13]);
            unsigned long long s7 = fadd2(zv[14], zv[15]);
            s0 = fadd2(s0, s1);  s2 = fadd2(s2, s3);
            s4 = fadd2(s4, s5);  s6 = fadd2(s6, s7);
            s0 = fadd2(s0, s2);  s4 = fadd2(s4, s6);
            s0 = fadd2(s0, s4);
            float lo, hi;
            unpack2(s0, lo, hi);
            float dp_b = lo + hi + bo;

            // Output sample (only after warmup)
            if (lane == 0 && t >= emit_beg) out[t] = 0.5f * (dp_a + dp_b);

            // Carry update (uniform across lanes — identical arithmetic order)
            b1 = fmaf(pB.x, dp_b, fmaf(pB.y, b1, pB.z));
            a0 = dp_b;
        }

        pA = nA;
        pB = nB;
    }
}

// ---------------------------------------------------------------------------
// Launch
// ---------------------------------------------------------------------------
extern "C" void kernel_launch(void* const* d_in, const int* in_sizes, int n_in,
                              void* d_out, int out_size) {
    const float* v_in  = (const float*)d_in[0];
    const float* vs_r  = (const float*)d_in[1];
    const float* fs    = (const float*)d_in[2];
    const float* W_in  = (const float*)d_in[3];
    const float* b_in  = (const float*)d_in[4];
    const float* W_h   = (const float*)d_in[5];
    const float* b_h   = (const float*)d_in[6];
    const float* W_out = (const float*)d_in[7];
    const float* b_out = (const float*)d_in[8];
    float* out = (float*)d_out;

    const int T = in_sizes[0];

    ndc_precompute_kernel<<<(T + 255) / 256, 256>>>(v_in, vs_r, fs, T);
    ndc_sequential_kernel<<<N_CHUNKS, 32>>>(W_in, b_in, W_h, b_h, W_out, b_out, out, T);
}

// round 8
// speedup vs baseline: 662.3795x; 2.8970x over previous
#include <cuda_runtime.h>
#include <cuda_bf16.h>

#define T_STEPS   480000
#define LAYER     32
#define C1_CONST  4.7e-9f
#define N_CHUNKS  1776     // 12 CTAs (warps) per SM x 148 SMs
#define WARMUP    512      // state-convergence warmup steps per chunk

// Per-step packed parameters (2 x float4 per step):
//  params[2t]   = { P0-1, P1,   P2*v, dp_r }
//  params[2t+1] = { P0,   P1-1, P2*v, 0    }
__device__ float4 g_params[2 * T_STEPS];

// ---------------------------------------------------------------------------
// packed f32x2 helpers (Blackwell FFMA2 path — only reachable via PTX)
// ---------------------------------------------------------------------------
__device__ __forceinline__ unsigned long long pack2(float lo, float hi) {
    unsigned long long r;
    asm("mov.b64 %0, {%1, %2};" : "=l"(r) : "f"(lo), "f"(hi));
    return r;
}
__device__ __forceinline__ void unpack2(unsigned long long v, float& lo, float& hi) {
    asm("mov.b64 {%0, %1}, %2;" : "=f"(lo), "=f"(hi) : "l"(v));
}
__device__ __forceinline__ unsigned long long ffma2(unsigned long long a,
                                                    unsigned long long b,
                                                    unsigned long long c) {
    unsigned long long d;
    asm("fma.rn.f32x2 %0, %1, %2, %3;" : "=l"(d) : "l"(a), "l"(b), "l"(c));
    return d;
}
__device__ __forceinline__ unsigned long long fadd2(unsigned long long a,
                                                    unsigned long long b) {
    unsigned long long d;
    asm("add.rn.f32x2 %0, %1, %2;" : "=l"(d) : "l"(a), "l"(b));
    return d;
}

// ---------------------------------------------------------------------------
// Kernel 1: parallel precompute of WDF port parameters
// ---------------------------------------------------------------------------
__global__ void ndc_precompute_kernel(const float* __restrict__ v_in,
                                      const float* __restrict__ vs_r,
                                      const float* __restrict__ fs,
                                      int T) {
    int t = blockIdx.x * blockDim.x + threadIdx.x;
    if (t >= T) return;

    float f  = fs[t];
    float vr = vs_r[t];
    float v  = v_in[t];

    float c1r = 1.0f / (2.0f * C1_CONST * f);
    float r0  = (c1r * vr) / (c1r + vr);

    float g0 = 1.0f / r0;
    float g1 = 1.0f / c1r;
    float g2 = 1.0f / vr;
    float inv2 = 2.0f / (g0 + g1 + g2);

    float P0 = g0 * inv2;
    float P1 = g1 * inv2;
    float P2 = g2 * inv2;

    float dpr = r0 * (1.0f / 3000.0f);

    g_params[2 * t]     = make_float4(P0 - 1.0f, P1,        P2 * v, dpr);
    g_params[2 * t + 1] = make_float4(P0,        P1 - 1.0f, P2 * v, 0.0f);
}

// ---------------------------------------------------------------------------
// 32x32 matvec for one lane: weights packed f32x2 in registers, activations
// broadcast from shared memory as 64-bit pairs. Returns row dot + bias.
// ---------------------------------------------------------------------------
__device__ __forceinline__ float matvec_row(const unsigned long long* __restrict__ wp,
                                            const unsigned long long* __restrict__ shp,
                                            float bias) {
    unsigned long long hv[16];
#pragma unroll
    for (int k = 0; k < 16; ++k) hv[k] = shp[k];

    unsigned long long acc0 = pack2(bias, 0.0f);
    unsigned long long acc1 = pack2(0.0f, 0.0f);
#pragma unroll
    for (int k = 0; k < 16; k += 2) {
        acc0 = ffma2(wp[k],     hv[k],     acc0);
        acc1 = ffma2(wp[k + 1], hv[k + 1], acc1);
    }
    acc0 = fadd2(acc0, acc1);
    float lo, hi;
    unpack2(acc0, lo, hi);
    return lo + hi;
}

// ---------------------------------------------------------------------------
// Kernel 2: chunk-parallel recurrence. One warp per chunk, 12 warps per SM.
// The WDF diode-clipper state contracts per step, so each chunk re-converges
// the carry with WARMUP steps from zero state. Chunk 0 is exact.
// ---------------------------------------------------------------------------
__global__ void __launch_bounds__(32, 12)
ndc_sequential_kernel(const float* __restrict__ W_in,   // [32,2]
                      const float* __restrict__ b_in,   // [32]
                      const float* __restrict__ W_h,    // [2,32,32]
                      const float* __restrict__ b_h,    // [2,32]
                      const float* __restrict__ W_out,  // [1,32]
                      const float* __restrict__ b_out,  // [1]
                      float* __restrict__ out,          // [T]
                      int T) {
    const int lane  = threadIdx.x;
    const int chunk = blockIdx.x;

    // Chunk bounds
    const int L        = (T + (int)gridDim.x - 1) / (int)gridDim.x;
    const int emit_beg = chunk * L;
    if (emit_beg >= T) return;
    const int emit_end = min(emit_beg + L, T);
    int t_begin        = emit_beg - WARMUP;
    if (t_begin < 0) t_begin = 0;

    __shared__ __align__(16) float sh0[LAYER];
    __shared__ __align__(16) float sh1[LAYER];
    __shared__ __align__(16) float sh2[LAYER];
    const unsigned long long* shp0 = (const unsigned long long*)sh0;
    const unsigned long long* shp1 = (const unsigned long long*)sh1;
    const unsigned long long* shp2 = (const unsigned long long*)sh2;

    // ---- load + pack weights into registers ----
    float win0 = W_in[lane * 2 + 0];
    float win1 = W_in[lane * 2 + 1];
    float bi   = b_in[lane];

    unsigned long long w1p[16], w2p[16];
#pragma unroll
    for (int k = 0; k < 16; ++k)
        w1p[k] = pack2(W_h[lane * LAYER + 2 * k], W_h[lane * LAYER + 2 * k + 1]);
#pragma unroll
    for (int k = 0; k < 16; ++k)
        w2p[k] = pack2(W_h[LAYER * LAYER + lane * LAYER + 2 * k],
                       W_h[LAYER * LAYER + lane * LAYER + 2 * k + 1]);

    float bh1 = b_h[lane];
    float bh2 = b_h[LAYER + lane];
    float wo  = W_out[lane];
    float bo  = b_out[0];

    // Carry (zero state; warmup converges it before emit_beg)
    float a0 = 0.0f;
    float b1 = 0.0f;

    // Prefetch first step's params
    float4 pA = g_params[2 * t_begin];
    float4 pB = g_params[2 * t_begin + 1];

    for (int t = t_begin; t < emit_end; ++t) {
        // Prefetch next step's params early (hide memory latency)
        int tn = (t + 1 < emit_end) ? (t + 1) : t;
        float4 nA = g_params[2 * tn];
        float4 nB = g_params[2 * tn + 1];

        // dp_a = row0 . [a0, b1, v]
        float dp_a = fmaf(pA.x, a0, fmaf(pA.y, b1, pA.z));

        // Input layer: scalar per lane
        float h = fmaxf(fmaf(win0, dp_a, fmaf(win1, pA.w, bi)), 0.0f);

        // Hidden layer 1 (smem broadcast + packed FMA)
        sh0[lane] = h;
        __syncwarp();
        float h1 = fmaxf(matvec_row(w1p, shp0, bh1), 0.0f);

        // Hidden layer 2
        sh1[lane] = h1;
        __syncwarp();
        float h2 = fmaxf(matvec_row(w2p, shp1, bh2), 0.0f);

        // Output layer: every lane redundantly sums wo[j]*h2[j] (packed add tree)
        sh2[lane] = wo * h2;
        __syncwarp();
        {
            unsigned long long zv[16];
#pragma unroll
            for (int k = 0; k < 16; ++k) zv[k] = shp2[k];
            unsigned long long s0 = fadd2(zv[0], zv[1]);
            unsigned long long s1 = fadd2(zv[2], zv[3]);
            unsigned long long s2 = fadd2(zv[4], zv[5]);
            unsigned long long s3 = fadd2(zv[6], zv[7]);
            unsigned long long s4 = fadd2(zv[8], zv[9]);
            unsigned long long s5 = fadd2(zv[10], zv[11]);
            unsigned long long s6 = fadd2(zv[12], zv[13]);
            unsigned long long s7 = fadd2(zv[14], zv[15]);
            s0 = fadd2(s0, s1);  s2 = fadd2(s2, s3);
            s4 = fadd2(s4, s5);  s6 = fadd2(s6, s7);
            s0 = fadd2(s0, s2);  s4 = fadd2(s4, s6);
            s0 = fadd2(s0, s4);
            float lo, hi;
            unpack2(s0, lo, hi);
            float dp_b = lo + hi + bo;

            // Output sample (only after warmup)
            if (lane == 0 && t >= emit_beg) out[t] = 0.5f * (dp_a + dp_b);

            // Carry update (uniform across lanes — identical arithmetic order)
            b1 = fmaf(pB.x, dp_b, fmaf(pB.y, b1, pB.z));
            a0 = dp_b;
        }

        pA = nA;
        pB = nB;
    }
}

// ---------------------------------------------------------------------------
// Launch
// ---------------------------------------------------------------------------
extern "C" void kernel_launch(void* const* d_in, const int* in_sizes, int n_in,
                              void* d_out, int out_size) {
    const float* v_in  = (const float*)d_in[0];
    const float* vs_r  = (const float*)d_in[1];
    const float* fs    = (const float*)d_in[2];
    const float* W_in  = (const float*)d_in[3];
    const float* b_in  = (const float*)d_in[4];
    const float* W_h   = (const float*)d_in[5];
    const float* b_h   = (const float*)d_in[6];
    const float* W_out = (const float*)d_in[7];
    const float* b_out = (const float*)d_in[8];
    float* out = (float*)d_out;

    const int T = in_sizes[0];

    ndc_precompute_kernel<<<(T + 255) / 256, 256>>>(v_in, vs_r, fs, T);
    ndc_sequential_kernel<<<N_CHUNKS, 32>>>(W_in, b_in, W_h, b_h, W_out, b_out, out, T);
}

// round 9
// speedup vs baseline: 1272.9240x; 1.9217x over previous
#include <cuda_runtime.h>
#include <cuda_bf16.h>

#define T_STEPS   480000
#define LAYER     32
#define C1_CONST  4.7e-9f
#define N_CHUNKS  1776     // 12 CTAs (warps) per SM x 148 SMs
#define WARMUP    128      // state-convergence warmup steps per chunk

// Per-step packed parameters (2 x float4 per step):
//  params[2t]   = { P0-1, P1,   P2*v, dp_r }
//  params[2t+1] = { P0,   P1-1, P2*v, 0    }
__device__ float4 g_params[2 * T_STEPS];

// ---------------------------------------------------------------------------
// packed f32x2 helpers (Blackwell FFMA2 path — only reachable via PTX)
// ---------------------------------------------------------------------------
__device__ __forceinline__ unsigned long long pack2(float lo, float hi) {
    unsigned long long r;
    asm("mov.b64 %0, {%1, %2};" : "=l"(r) : "f"(lo), "f"(hi));
    return r;
}
__device__ __forceinline__ void unpack2(unsigned long long v, float& lo, float& hi) {
    asm("mov.b64 {%0, %1}, %2;" : "=f"(lo), "=f"(hi) : "l"(v));
}
__device__ __forceinline__ unsigned long long ffma2(unsigned long long a,
                                                    unsigned long long b,
                                                    unsigned long long c) {
    unsigned long long d;
    asm("fma.rn.f32x2 %0, %1, %2, %3;" : "=l"(d) : "l"(a), "l"(b), "l"(c));
    return d;
}
__device__ __forceinline__ unsigned long long fadd2(unsigned long long a,
                                                    unsigned long long b) {
    unsigned long long d;
    asm("add.rn.f32x2 %0, %1, %2;" : "=l"(d) : "l"(a), "l"(b));
    return d;
}

// ---------------------------------------------------------------------------
// Kernel 1: parallel precompute of WDF port parameters
// ---------------------------------------------------------------------------
__global__ void ndc_precompute_kernel(const float* __restrict__ v_in,
                                      const float* __restrict__ vs_r,
                                      const float* __restrict__ fs,
                                      int T) {
    int t = blockIdx.x * blockDim.x + threadIdx.x;
    if (t >= T) return;

    float f  = fs[t];
    float vr = vs_r[t];
    float v  = v_in[t];

    float c1r = 1.0f / (2.0f * C1_CONST * f);
    float r0  = (c1r * vr) / (c1r + vr);

    float g0 = 1.0f / r0;
    float g1 = 1.0f / c1r;
    float g2 = 1.0f / vr;
    float inv2 = 2.0f / (g0 + g1 + g2);

    float P0 = g0 * inv2;
    float P1 = g1 * inv2;
    float P2 = g2 * inv2;

    float dpr = r0 * (1.0f / 3000.0f);

    g_params[2 * t]     = make_float4(P0 - 1.0f, P1,        P2 * v, dpr);
    g_params[2 * t + 1] = make_float4(P0,        P1 - 1.0f, P2 * v, 0.0f);
}

// ---------------------------------------------------------------------------
// 32x32 matvec for one lane: weights packed f32x2 in registers, activations
// broadcast from shared memory via 128-bit vector loads (8 LDS.128).
// ---------------------------------------------------------------------------
__device__ __forceinline__ float matvec_row(const unsigned long long* __restrict__ wp,
                                            const uint4* __restrict__ shp,
                                            float bias) {
    uint4 hv[8];
#pragma unroll
    for (int k = 0; k < 8; ++k) hv[k] = shp[k];

    unsigned long long acc0 = pack2(bias, 0.0f);
    unsigned long long acc1 = pack2(0.0f, 0.0f);
#pragma unroll
    for (int k = 0; k < 8; ++k) {
        unsigned long long lo = pack2(__uint_as_float(hv[k].x), __uint_as_float(hv[k].y));
        unsigned long long hi = pack2(__uint_as_float(hv[k].z), __uint_as_float(hv[k].w));
        acc0 = ffma2(wp[2 * k],     lo, acc0);
        acc1 = ffma2(wp[2 * k + 1], hi, acc1);
    }
    acc0 = fadd2(acc0, acc1);
    float lo, hi;
    unpack2(acc0, lo, hi);
    return lo + hi;
}

// ---------------------------------------------------------------------------
// Kernel 2: chunk-parallel recurrence. One warp per chunk, 12 warps per SM.
// The WDF diode-clipper state contracts per step (|Jacobian| ~ 0.2-0.6),
// so each chunk re-converges the carry with WARMUP steps from zero state.
// Chunk 0 is exact.
// ---------------------------------------------------------------------------
__global__ void __launch_bounds__(32, 12)
ndc_sequential_kernel(const float* __restrict__ W_in,   // [32,2]
                      const float* __restrict__ b_in,   // [32]
                      const float* __restrict__ W_h,    // [2,32,32]
                      const float* __restrict__ b_h,    // [2,32]
                      const float* __restrict__ W_out,  // [1,32]
                      const float* __restrict__ b_out,  // [1]
                      float* __restrict__ out,          // [T]
                      int T) {
    const int lane  = threadIdx.x;
    const int chunk = blockIdx.x;
    const unsigned FULL = 0xffffffffu;

    // Chunk bounds
    const int L        = (T + (int)gridDim.x - 1) / (int)gridDim.x;
    const int emit_beg = chunk * L;
    if (emit_beg >= T) return;
    const int emit_end = min(emit_beg + L, T);
    int t_begin        = emit_beg - WARMUP;
    if (t_begin < 0) t_begin = 0;

    __shared__ __align__(16) float sh0[LAYER];
    __shared__ __align__(16) float sh1[LAYER];
    const uint4* shp0 = (const uint4*)sh0;
    const uint4* shp1 = (const uint4*)sh1;

    // ---- load + pack weights into registers ----
    float win0 = W_in[lane * 2 + 0];
    float win1 = W_in[lane * 2 + 1];
    float bi   = b_in[lane];

    unsigned long long w1p[16], w2p[16];
#pragma unroll
    for (int k = 0; k < 16; ++k)
        w1p[k] = pack2(W_h[lane * LAYER + 2 * k], W_h[lane * LAYER + 2 * k + 1]);
#pragma unroll
    for (int k = 0; k < 16; ++k)
        w2p[k] = pack2(W_h[LAYER * LAYER + lane * LAYER + 2 * k],
                       W_h[LAYER * LAYER + lane * LAYER + 2 * k + 1]);

    float bh1 = b_h[lane];
    float bh2 = b_h[LAYER + lane];
    float wo  = W_out[lane];
    float bo  = b_out[0];

    // Carry (zero state; warmup converges it before emit_beg)
    float a0 = 0.0f;
    float b1 = 0.0f;

    // Prefetch first step's params
    float4 pA = g_params[2 * t_begin];
    float4 pB = g_params[2 * t_begin + 1];

    for (int t = t_begin; t < emit_end; ++t) {
        // Prefetch next step's params early (hide memory latency)
        int tn = (t + 1 < emit_end) ? (t + 1) : t;
        float4 nA = g_params[2 * tn];
        float4 nB = g_params[2 * tn + 1];

        // dp_a = row0 . [a0, b1, v]
        float dp_a = fmaf(pA.x, a0, fmaf(pA.y, b1, pA.z));

        // Input layer: scalar per lane
        float h = fmaxf(fmaf(win0, dp_a, fmaf(win1, pA.w, bi)), 0.0f);

        // Hidden layer 1 (smem broadcast + packed FMA)
        sh0[lane] = h;
        __syncwarp();
        float h1 = fmaxf(matvec_row(w1p, shp0, bh1), 0.0f);

        // Hidden layer 2
        sh1[lane] = h1;
        __syncwarp();
        float h2 = fmaxf(matvec_row(w2p, shp1, bh2), 0.0f);

        // Output layer: butterfly reduction (fp add commutes -> result is
        // bitwise-identical across lanes, so the carry stays uniform).
        float y = wo * h2;
        y += __shfl_xor_sync(FULL, y, 16);
        y += __shfl_xor_sync(FULL, y, 8);
        y += __shfl_xor_sync(FULL, y, 4);
        y += __shfl_xor_sync(FULL, y, 2);
        y += __shfl_xor_sync(FULL, y, 1);
        float dp_b = y + bo;

        // Output sample (only after warmup)
        if (lane == 0 && t >= emit_beg) out[t] = 0.5f * (dp_a + dp_b);

        // Carry update (uniform across lanes)
        b1 = fmaf(pB.x, dp_b, fmaf(pB.y, b1, pB.z));
        a0 = dp_b;

        pA = nA;
        pB = nB;
    }
}

// ---------------------------------------------------------------------------
// Launch
// ---------------------------------------------------------------------------
extern "C" void kernel_launch(void* const* d_in, const int* in_sizes, int n_in,
                              void* d_out, int out_size) {
    const float* v_in  = (const float*)d_in[0];
    const float* vs_r  = (const float*)d_in[1];
    const float* fs    = (const float*)d_in[2];
    const float* W_in  = (const float*)d_in[3];
    const float* b_in  = (const float*)d_in[4];
    const float* W_h   = (const float*)d_in[5];
    const float* b_h   = (const float*)d_in[6];
    const float* W_out = (const float*)d_in[7];
    const float* b_out = (const float*)d_in[8];
    float* out = (float*)d_out;

    const int T = in_sizes[0];

    ndc_precompute_kernel<<<(T + 255) / 256, 256>>>(v_in, vs_r, fs, T);
    ndc_sequential_kernel<<<N_CHUNKS, 32>>>(W_in, b_in, W_h, b_h, W_out, b_out, out, T);
}